// round 11
// baseline (speedup 1.0000x reference)
#include <cuda_runtime.h>
#include <cuda_bf16.h>

#define BB 16
#define TT 800
#define VV 4000
#define LL 100
#define SS 201        // 2L+1 states
#define EW 208        // emission row stride (floats): 832B rows
#define BUF 1728      // shared buffer floats: 8*EW + 64 pad
#define NEGV (-1e30f)
#define LAMB 0.1f
#define LN2D 0.6931471805599453094
#define ADOPT_BLKS 14 // full renorm (zero-lane adoption) for first 14 blocks
#define DPB 16        // DP CTAs at the front of the grid

// Scratch (__device__ globals per allocation-free rule)
__device__ float g_lse[BB * TT];
__device__ float g_m2[BB * TT];
__device__ __align__(16) float g_em[(size_t)BB * TT * EW];  // 10.6 MB
__device__ float g_cost[BB];
__device__ int g_cnt;            // finalize arrival counter (self-resetting)
__device__ int g_flag[BB * TT];  // per-(b,t) row-ready flags (reset each run)

__inline__ __device__ float warp_max(float v) {
#pragma unroll
    for (int o = 16; o; o >>= 1) v = fmaxf(v, __shfl_xor_sync(0xffffffffu, v, o));
    return v;
}
__inline__ __device__ float warp_sum(float v) {
#pragma unroll
    for (int o = 16; o; o >>= 1) v += __shfl_xor_sync(0xffffffffu, v, o);
    return v;
}
__device__ __forceinline__ unsigned smem_u32(const void* p) {
    return (unsigned)__cvta_generic_to_shared(p);
}
__device__ __forceinline__ void cp_async16(unsigned dst, const void* src) {
    asm volatile("cp.async.cg.shared.global [%0], [%1], 16;" :: "r"(dst), "l"(src) : "memory");
}
__device__ __forceinline__ int ld_acq(const int* p) {
    int v;
    asm volatile("ld.global.acquire.gpu.b32 %0, [%1];" : "=r"(v) : "l"(p) : "memory");
    return v;
}
// Spin until rows [lo, lo+n) of batch b are produced (lanes 0..n-1 poll).
__device__ __forceinline__ void wait_rows(int b, int lo, int n) {
    const int lane = threadIdx.x & 31;
    const int* f = g_flag + b * TT + lo + lane;
    if (lane < n) {
        while (ld_acq(f) == 0) __nanosleep(128);
    }
    __syncwarp();
}

// ============================================================================
// Kernel 0: reset consumed state (flags + counter) — graph-replay determinism
// ============================================================================
__global__ void reset_kernel() {
    const int i = blockIdx.x * blockDim.x + threadIdx.x;
    if (i < BB * TT) g_flag[i] = 0;
    if (i == 0) g_cnt = 0;
}

// ============================================================================
// DP step / renorm machinery (validated rounds 5-10)
// ============================================================================
__device__ __forceinline__ void dpstep32r(float v[8], float4 e0, float4 e1,
                                          int lane, float m1, float m3, float m5,
                                          float m7, float fD) {
    float hi1 = __shfl_up_sync(0xffffffffu, v[7], 1);
    const float hiX = (lane == 0) ? 0.0f : hi1 * fD;
    const float u7 = fmaf(m7, v[5], v[6]);
    const float u5 = fmaf(m5, v[3], v[4]);
    const float u3 = fmaf(m3, v[1], v[2]);
    const float u1 = fmaf(m1, hiX, v[0]);
    v[7] = fmaf(v[7], e1.w, u7 * e1.w);
    v[6] = fmaf(v[6], e1.z, v[5] * e1.z);
    v[5] = fmaf(v[5], e1.y, u5 * e1.y);
    v[4] = fmaf(v[4], e1.x, v[3] * e1.x);
    v[3] = fmaf(v[3], e0.w, u3 * e0.w);
    v[2] = fmaf(v[2], e0.z, v[1] * e0.z);
    v[1] = fmaf(v[1], e0.y, u1 * e0.y);
    v[0] = fmaf(v[0], e0.x, hiX * e0.x);
}

__device__ __forceinline__ void bstep32r(float b[8], float4 e0, float4 e1,
                                         int lane, float a1, float a3, float a5,
                                         float a7, float fD) {
    const float w0 = b[0] * e0.x, w1 = b[1] * e0.y, w2 = b[2] * e0.z, w3 = b[3] * e0.w;
    const float w4 = b[4] * e1.x, w5 = b[5] * e1.y, w6 = b[6] * e1.z, w7 = b[7] * e1.w;
    float h0 = __shfl_down_sync(0xffffffffu, w0, 1);
    float h1 = __shfl_down_sync(0xffffffffu, w1, 1);
    if (lane == 31) { h0 = 0.0f; h1 = 0.0f; }
    h0 *= fD; h1 *= fD;
    b[0] = w0 + w1;
    b[1] = fmaf(a1, w3, w1 + w2);
    b[2] = w2 + w3;
    b[3] = fmaf(a3, w5, w3 + w4);
    b[4] = w4 + w5;
    b[5] = fmaf(a5, w7, w5 + w6);
    b[6] = w6 + w7;
    b[7] = fmaf(a7, h1, w7 + h0);
}

__device__ __forceinline__ int renorm_local(float v[8]) {
    float m = 0.0f;
#pragma unroll
    for (int j = 0; j < 8; j++) m = fmaxf(m, v[j]);
    if (m == 0.0f) return 0x40000000;
    const int e = ((__float_as_int(m) >> 23) & 255) - 127;
    const float f = __int_as_float((unsigned)(127 - e) << 23);
#pragma unroll
    for (int j = 0; j < 8; j++) v[j] *= f;
    return e;
}

__device__ __forceinline__ void renormF(float v[8], int& ex, int lane, float& fD) {
    const int e = renorm_local(v);
    int zi = (e == 0x40000000) ? 1 : 0;
    if (!zi) ex += e;
#pragma unroll
    for (int d = 1; d <= 4; d <<= 1) {
        const int exu = __shfl_up_sync(0xffffffffu, ex, d);
        const int zu = __shfl_up_sync(0xffffffffu, zi, d);
        if (lane >= d && zi) { ex = exu; zi = zu; }
    }
    const int exl = __shfl_up_sync(0xffffffffu, ex, 1);
    int dlt = (lane == 0) ? 0 : (exl - ex);
    dlt = max(-126, min(112, dlt));
    fD = __int_as_float((unsigned)(dlt + 127) << 23);
}
__device__ __forceinline__ void renormFc(float v[8], int& ex, int lane, float& fD) {
    const int e = renorm_local(v);
    if (e != 0x40000000) ex += e;
    const int exl = __shfl_up_sync(0xffffffffu, ex, 1);
    int dlt = (lane == 0) ? 0 : (exl - ex);
    dlt = max(-126, min(112, dlt));
    fD = __int_as_float((unsigned)(dlt + 127) << 23);
}
__device__ __forceinline__ void renormB(float v[8], int& ex, int lane, float& fD) {
    const int e = renorm_local(v);
    int zi = (e == 0x40000000) ? 1 : 0;
    if (!zi) ex += e;
#pragma unroll
    for (int d = 1; d <= 4; d <<= 1) {
        const int exd = __shfl_down_sync(0xffffffffu, ex, d);
        const int zd = __shfl_down_sync(0xffffffffu, zi, d);
        if (lane < 32 - d && zi) { ex = exd; zi = zd; }
    }
    const int exr = __shfl_down_sync(0xffffffffu, ex, 1);
    int dlt = (lane == 31) ? 0 : (exr - ex);
    dlt = max(-126, min(112, dlt));
    fD = __int_as_float((unsigned)(dlt + 127) << 23);
}
__device__ __forceinline__ void renormBc(float v[8], int& ex, int lane, float& fD) {
    const int e = renorm_local(v);
    if (e != 0x40000000) ex += e;
    const int exr = __shfl_down_sync(0xffffffffu, ex, 1);
    int dlt = (lane == 31) ? 0 : (exr - ex);
    dlt = max(-126, min(112, dlt));
    fD = __int_as_float((unsigned)(dlt + 127) << 23);
}

// ============================================================================
// Fused kernel: blockIdx < DPB -> DP consumer CTA (one per batch);
// else -> producer CTA for row (b, t), t-major so all batches advance together.
// Producers: single-pass lse + gather + linear emissions, then release a flag.
// Consumers: bidirectional DP (fwd warp 0 covers 0..c with c = 0.73*len since
// backward can only start once t=len-1 is produced; bwd warp 1; den warp 2),
// spinning on flags per 8-row block. Fused finalize: last CTA writes out.
// ============================================================================
__global__ __launch_bounds__(256) void fused_kernel(
    const float* __restrict__ logits, const int* __restrict__ labels,
    const int* __restrict__ input_lengths, const int* __restrict__ label_lengths,
    float* __restrict__ out) {
    const int tid = threadIdx.x;
    const int lane = tid & 31;

    if (blockIdx.x >= DPB) {
        // ---------------- producer ----------------
        const int lin = blockIdx.x - DPB;
        const int t = lin >> 4, b = lin & 15;
        if (t >= __ldg(input_lengths + b)) return;  // dead row: never consumed

        const int bt = b * TT + t;
        const float* __restrict__ row = logits + (size_t)bt * VV;
        const int wid = tid >> 5;

        float s = 0.0f;
#pragma unroll
        for (int i = 0; i < 4; i++) {
            int idx = tid + i * 256;
            if (idx < VV / 4) {
                float4 v = reinterpret_cast<const float4*>(row)[idx];
                s += __expf(v.x) + __expf(v.y) + __expf(v.z) + __expf(v.w);
            }
        }
        __shared__ float ssum[8], sgm[8];
        s = warp_sum(s);
        if (lane == 0) ssum[wid] = s;

        float val = NEGV;
        if (tid <= 200) {
            int vv = (tid & 1) ? labels[b * LL + (tid >> 1)] : 0;
            val = __ldg(row + vv);
        }
        float gm = warp_max(val);
        if (lane == 0) sgm[wid] = gm;
        __syncthreads();

        s = ssum[0];
        gm = sgm[0];
#pragma unroll
        for (int i = 1; i < 8; i++) { s += ssum[i]; gm = fmaxf(gm, sgm[i]); }
        const float lse = __logf(s);

        if (tid < EW)
            g_em[(size_t)bt * EW + tid] = (tid <= 200) ? __expf(val - gm) : 0.0f;
        if (tid == 0) {
            g_lse[bt] = lse;
            g_m2[bt] = gm - lse;
        }
        // release: all writes visible before the flag
        __threadfence();
        __syncthreads();
        if (tid == 0) atomicExch(&g_flag[bt], 1);
        return;
    }

    // ---------------- DP consumer CTA ----------------
    const int b = blockIdx.x;
    const int w = tid >> 5;

    __shared__ __align__(16) float eshf[2][BUF];
    __shared__ __align__(16) float eshb[2][BUF];
    __shared__ float sB[256];
    __shared__ int sExB[32];
    __shared__ float s_den, s_corr, s_tot;
    __shared__ int s_ex;

    const int len = input_lengths[b];
    int c = (len * 187) >> 8;                // ~0.73*len: backward starts late
    if (c > len - 2) c = len - 2;
    const char* gbase = (const char*)(g_em + (size_t)b * TT * EW);

    float vF[8];
    int exF = 0;

    if (w == 2) {
        // ---- denominator sums, chasing production per 32-row chunk ----
        float d = 0.0f, cc = 0.0f;
        for (int base = 0; base < len; base += 32) {
            const int n = min(32, len - base);
            wait_rows(b, base, n);
            if (lane < n) {
                d += g_lse[b * TT + base + lane];
                cc += g_m2[b * TT + base + lane];
            }
        }
        d = warp_sum(d);
        cc = warp_sum(cc);
        if (lane == 0) { s_den = d; s_corr = cc; }
    } else if (w == 0) {
        // ---------------- forward warp ----------------
        eshf[0][8 * EW + lane] = 0.0f; eshf[0][8 * EW + 32 + lane] = 0.0f;
        eshf[1][8 * EW + lane] = 0.0f; eshf[1][8 * EW + 32 + lane] = 0.0f;
        __syncwarp();

        const int s0 = lane * 8;
        float m1 = 0, m3 = 0, m5 = 0, m7 = 0;
        {
            const int* lb = labels + b * LL;
#pragma unroll
            for (int j = 1; j < 8; j += 2) {
                int s = s0 + j;
                float a = 0.0f;
                if (s >= 3 && s <= 200) {
                    int i = s >> 1;
                    a = (lb[i] != lb[i - 1]) ? 1.0f : 0.0f;
                }
                if (j == 1) m1 = a; else if (j == 3) m3 = a;
                else if (j == 5) m5 = a; else m7 = a;
            }
        }

        const unsigned ebase = smem_u32(&eshf[0][0]);
        const int rf = c + 1;                 // rows 0..c
        const int nbf = (rf + 7) >> 3;

#define ISSUE_F(ib) do {                                                         \
        if ((ib) < nbf) {                                                        \
            const char* _s = gbase + (size_t)(ib) * 6656 + lane * 16;            \
            unsigned _d = ebase + (((ib) & 1) * (BUF * 4)) + lane * 16;          \
            _Pragma("unroll")                                                    \
            for (int _k = 0; _k < 13; _k++) cp_async16(_d + _k * 512, _s + _k * 512); \
        }                                                                        \
        asm volatile("cp.async.commit_group;" ::: "memory");                     \
    } while (0)

        wait_rows(b, 0, min(8, rf));
        ISSUE_F(0);
        if (1 < nbf) wait_rows(b, 8, min(8, rf - 8));
        ISSUE_F(1);

#pragma unroll
        for (int j = 0; j < 8; j++) vF[j] = 0.0f;
        float fD = 1.0f;

        for (int ib = 0; ib < nbf; ib++) {
            asm volatile("cp.async.wait_group 1;" ::: "memory");
            const float* base = &eshf[ib & 1][0];
            const float* lp = base + lane * 8;
            const int lim = min(8, rf - ib * 8);
            if (ib == 0) {
                if (lane == 0) { vF[0] = base[0]; vF[1] = base[1]; }
                float4 c0 = *(const float4*)(lp + EW);
                float4 c1 = *(const float4*)(lp + EW + 4);
#pragma unroll
                for (int tt = 1; tt < 8; tt++) {
                    float4 n0 = c0, n1 = c1;
                    if (tt < 7) {
                        n0 = *(const float4*)(lp + (tt + 1) * EW);
                        n1 = *(const float4*)(lp + (tt + 1) * EW + 4);
                    }
                    dpstep32r(vF, c0, c1, lane, m1, m3, m5, m7, fD);
                    c0 = n0; c1 = n1;
                }
            } else if (lim == 8) {
                float4 c0 = *(const float4*)(lp);
                float4 c1 = *(const float4*)(lp + 4);
#pragma unroll
                for (int tt = 0; tt < 8; tt++) {
                    float4 n0 = c0, n1 = c1;
                    if (tt < 7) {
                        n0 = *(const float4*)(lp + (tt + 1) * EW);
                        n1 = *(const float4*)(lp + (tt + 1) * EW + 4);
                    }
                    dpstep32r(vF, c0, c1, lane, m1, m3, m5, m7, fD);
                    c0 = n0; c1 = n1;
                }
            } else {
                for (int tt = 0; tt < lim; tt++) {
                    float4 e0 = *(const float4*)(lp + tt * EW);
                    float4 e1 = *(const float4*)(lp + tt * EW + 4);
                    dpstep32r(vF, e0, e1, lane, m1, m3, m5, m7, fD);
                }
            }
            if (ib < ADOPT_BLKS) renormF(vF, exF, lane, fD);
            else renormFc(vF, exF, lane, fD);
            if (ib + 2 < nbf) wait_rows(b, 8 * (ib + 2), min(8, rf - 8 * (ib + 2)));
            ISSUE_F(ib + 2);
        }
    } else if (w == 1) {
        // ---------------- backward warp ----------------
        eshb[0][8 * EW + lane] = 0.0f; eshb[0][8 * EW + 32 + lane] = 0.0f;
        eshb[1][8 * EW + lane] = 0.0f; eshb[1][8 * EW + 32 + lane] = 0.0f;
        __syncwarp();

        const int s0 = lane * 8;
        float a1 = 0, a3 = 0, a5 = 0, a7 = 0;  // allow(s+2) for odd j
        {
            const int* lb = labels + b * LL;
#pragma unroll
            for (int j = 1; j < 8; j += 2) {
                int sp = s0 + j + 2;
                float a = 0.0f;
                if (sp <= 200) {
                    int i = sp >> 1;
                    a = (lb[i] != lb[i - 1]) ? 1.0f : 0.0f;
                }
                if (j == 1) a1 = a; else if (j == 3) a3 = a;
                else if (j == 5) a5 = a; else a7 = a;
            }
        }

        const unsigned ebase = smem_u32(&eshb[0][0]);
        const int rb = len - 1 - c;               // rows len-1 .. c+1
        const int nbb = (rb + 7) >> 3;

        // block k stages rows [len-8-8k .. len-1-8k]; all valid (>=c-6>=0)
#define ISSUE_B(k) do {                                                          \
        if ((k) < nbb) {                                                         \
            const char* _s = gbase + (size_t)(len - 8 - 8 * (k)) * 832 + lane * 16; \
            unsigned _d = ebase + (((k) & 1) * (BUF * 4)) + lane * 16;           \
            _Pragma("unroll")                                                    \
            for (int _k = 0; _k < 13; _k++) cp_async16(_d + _k * 512, _s + _k * 512); \
        }                                                                        \
        asm volatile("cp.async.commit_group;" ::: "memory");                     \
    } while (0)

        wait_rows(b, len - 8, 8);
        ISSUE_B(0);
        if (1 < nbb) wait_rows(b, len - 16, 8);
        ISSUE_B(1);

        const int end = 2 * label_lengths[b];
        float vB[8];
#pragma unroll
        for (int j = 0; j < 8; j++) {
            int s = s0 + j;
            vB[j] = (s == end || s == end - 1) ? 1.0f : 0.0f;
        }
        int exB = 0;
        float fD = 1.0f;

        for (int k = 0; k < nbb; k++) {
            asm volatile("cp.async.wait_group 1;" ::: "memory");
            const float* base = &eshb[k & 1][0];
            const float* lp = base + lane * 8;
            const int hi = len - 1 - 8 * k;
            const int lim = min(8, hi - c);       // consume rows hi..hi-lim+1
            if (lim == 8) {
                float4 c0 = *(const float4*)(lp + 7 * EW);
                float4 c1 = *(const float4*)(lp + 7 * EW + 4);
#pragma unroll
                for (int tt = 0; tt < 8; tt++) {
                    float4 n0 = c0, n1 = c1;
                    if (tt < 7) {
                        n0 = *(const float4*)(lp + (6 - tt) * EW);
                        n1 = *(const float4*)(lp + (6 - tt) * EW + 4);
                    }
                    bstep32r(vB, c0, c1, lane, a1, a3, a5, a7, fD);
                    c0 = n0; c1 = n1;
                }
            } else {
                for (int tt = 0; tt < lim; tt++) {
                    float4 e0 = *(const float4*)(lp + (7 - tt) * EW);
                    float4 e1 = *(const float4*)(lp + (7 - tt) * EW + 4);
                    bstep32r(vB, e0, e1, lane, a1, a3, a5, a7, fD);
                }
            }
            if (k < ADOPT_BLKS) renormB(vB, exB, lane, fD);
            else renormBc(vB, exB, lane, fD);
            if (k + 2 < nbb) wait_rows(b, len - 8 - 8 * (k + 2), 8);
            ISSUE_B(k + 2);
        }

        // publish beta_c frames
#pragma unroll
        for (int j = 0; j < 8; j++) sB[s0 + j] = vB[j];
        sExB[lane] = exB;
    }
    __syncthreads();

    if (w == 0) {
        // Total = sum_s alpha_c[s] * beta_c[s]
        float p = 0.0f;
        const int s0 = lane * 8;
#pragma unroll
        for (int j = 0; j < 8; j++) p += vF[j] * sB[s0 + j];
        const int e = exF + sExB[lane];
        int exv = (p > 0.0f) ? e : (int)0xC0000000;
        int exm = exv;
#pragma unroll
        for (int o = 16; o; o >>= 1) exm = max(exm, __shfl_xor_sync(0xffffffffu, exm, o));
        float a = (p > 0.0f) ? p * exp2f((float)(e - exm)) : 0.0f;
        a = warp_sum(a);
        if (lane == 0) { s_tot = a; s_ex = exm; }
    }
    __syncthreads();
    if (tid == 0) {
        const double lognum = log((double)s_tot) + (double)s_ex * LN2D + (double)s_corr;
        const float nll = -(float)lognum;
        g_cost[b] = s_den - (1.0f + LAMB) * nll;

        __threadfence();
        const int arrived = atomicAdd(&g_cnt, 1);
        if (arrived == BB - 1) {
            float s = 0.0f;
#pragma unroll
            for (int i = 0; i < BB; i++) s += g_cost[i];
            out[0] = s / (float)BB;
            g_cnt = 0;  // reset for next replay
        }
    }
}

extern "C" void kernel_launch(void* const* d_in, const int* in_sizes, int n_in,
                              void* d_out, int out_size) {
    const float* logits = (const float*)d_in[0];
    const int* labels = (const int*)d_in[1];
    const int* input_lengths = (const int*)d_in[2];
    const int* label_lengths = (const int*)d_in[3];
    float* out = (float*)d_out;

    reset_kernel<<<(BB * TT + 255) / 256, 256>>>();
    fused_kernel<<<DPB + BB * TT, 256>>>(logits, labels, input_lengths,
                                         label_lengths, out);
}

// round 12
// speedup vs baseline: 1.2858x; 1.2858x over previous
#include <cuda_runtime.h>
#include <cuda_bf16.h>

#define BB 16
#define TT 800
#define VV 4000
#define LL 100
#define SS 201        // 2L+1 states
#define EW 208        // emission row stride (floats): 832B rows
#define BUF 1728      // shared buffer floats: 8*EW + 64 pad
#define NEGV (-1e30f)
#define LAMB 0.1f
#define LN2D 0.6931471805599453094
#define ADOPT_BLKS 14 // full renorm (zero-lane adoption) for first 14 blocks

// Scratch (__device__ globals per allocation-free rule)
__device__ float g_lse[BB * TT];
__device__ float g_m2[BB * TT];
__device__ __align__(16) float g_em[(size_t)BB * TT * EW];  // 10.6 MB
__device__ float g_cost[BB];
__device__ int g_cnt;            // finalize arrival counter (self-resetting)
__device__ int g_flag[BB * TT];  // per-(b,t) row-ready flags

__inline__ __device__ float warp_max(float v) {
#pragma unroll
    for (int o = 16; o; o >>= 1) v = fmaxf(v, __shfl_xor_sync(0xffffffffu, v, o));
    return v;
}
__inline__ __device__ float warp_sum(float v) {
#pragma unroll
    for (int o = 16; o; o >>= 1) v += __shfl_xor_sync(0xffffffffu, v, o);
    return v;
}
__device__ __forceinline__ unsigned smem_u32(const void* p) {
    return (unsigned)__cvta_generic_to_shared(p);
}
__device__ __forceinline__ void cp_async16(unsigned dst, const void* src) {
    asm volatile("cp.async.cg.shared.global [%0], [%1], 16;" :: "r"(dst), "l"(src) : "memory");
}
__device__ __forceinline__ int ld_acq(const int* p) {
    int v;
    asm volatile("ld.global.acquire.gpu.b32 %0, [%1];" : "=r"(v) : "l"(p) : "memory");
    return v;
}
// Spin until rows [lo, lo+n) of batch b are produced (lanes 0..n-1 poll).
__device__ __forceinline__ void wait_rows(int b, int lo, int n) {
    const int lane = threadIdx.x & 31;
    const int* f = g_flag + b * TT + lo + lane;
    if (lane < n) {
        while (ld_acq(f) == 0) __nanosleep(128);
    }
    __syncwarp();
}

// ============================================================================
// Kernel 0: reset consumed state (flags + counter) — graph-replay determinism
// ============================================================================
__global__ void reset_kernel() {
    const int i = blockIdx.x * blockDim.x + threadIdx.x;
    if (i < BB * TT) g_flag[i] = 0;
    if (i == 0) g_cnt = 0;
}

// ============================================================================
// Producer kernel (own compilation unit = round-10 codegen): per-(b,t)
// single-pass lse + gather -> linear emissions, then release row flag.
// 1D grid, t-major: lin = t*16 + b so all batches advance together in t.
// ============================================================================
__global__ __launch_bounds__(256) void producer_kernel(
    const float* __restrict__ logits, const int* __restrict__ labels,
    const int* __restrict__ input_lengths) {
    const int lin = blockIdx.x;
    const int t = lin >> 4, b = lin & 15;
    if (t >= __ldg(input_lengths + b)) return;  // dead row: never consumed

    const int bt = b * TT + t;
    const float* __restrict__ row = logits + (size_t)bt * VV;
    const int tid = threadIdx.x;
    const int lane = tid & 31, wid = tid >> 5;

    float s = 0.0f;
#pragma unroll
    for (int i = 0; i < 4; i++) {
        int idx = tid + i * 256;
        if (idx < VV / 4) {
            float4 v = reinterpret_cast<const float4*>(row)[idx];
            s += __expf(v.x) + __expf(v.y) + __expf(v.z) + __expf(v.w);
        }
    }
    __shared__ float ssum[8], sgm[8];
    s = warp_sum(s);
    if (lane == 0) ssum[wid] = s;

    float val = NEGV;
    if (tid <= 200) {
        int vv = (tid & 1) ? labels[b * LL + (tid >> 1)] : 0;
        val = __ldg(row + vv);
    }
    float gm = warp_max(val);
    if (lane == 0) sgm[wid] = gm;
    __syncthreads();

    s = ssum[0];
    gm = sgm[0];
#pragma unroll
    for (int i = 1; i < 8; i++) { s += ssum[i]; gm = fmaxf(gm, sgm[i]); }
    const float lse = __logf(s);

    if (tid < EW)
        g_em[(size_t)bt * EW + tid] = (tid <= 200) ? __expf(val - gm) : 0.0f;
    if (tid == 0) {
        g_lse[bt] = lse;
        g_m2[bt] = gm - lse;
    }
    // release: every thread fences its writes, then one flag after the barrier
    __threadfence();
    __syncthreads();
    if (tid == 0) atomicExch(&g_flag[bt], 1);
}

// ============================================================================
// DP machinery (validated rounds 5-10)
// ============================================================================
__device__ __forceinline__ void dpstep32r(float v[8], float4 e0, float4 e1,
                                          int lane, float m1, float m3, float m5,
                                          float m7, float fD) {
    float hi1 = __shfl_up_sync(0xffffffffu, v[7], 1);
    const float hiX = (lane == 0) ? 0.0f : hi1 * fD;
    const float u7 = fmaf(m7, v[5], v[6]);
    const float u5 = fmaf(m5, v[3], v[4]);
    const float u3 = fmaf(m3, v[1], v[2]);
    const float u1 = fmaf(m1, hiX, v[0]);
    v[7] = fmaf(v[7], e1.w, u7 * e1.w);
    v[6] = fmaf(v[6], e1.z, v[5] * e1.z);
    v[5] = fmaf(v[5], e1.y, u5 * e1.y);
    v[4] = fmaf(v[4], e1.x, v[3] * e1.x);
    v[3] = fmaf(v[3], e0.w, u3 * e0.w);
    v[2] = fmaf(v[2], e0.z, v[1] * e0.z);
    v[1] = fmaf(v[1], e0.y, u1 * e0.y);
    v[0] = fmaf(v[0], e0.x, hiX * e0.x);
}

__device__ __forceinline__ void bstep32r(float b[8], float4 e0, float4 e1,
                                         int lane, float a1, float a3, float a5,
                                         float a7, float fD) {
    const float w0 = b[0] * e0.x, w1 = b[1] * e0.y, w2 = b[2] * e0.z, w3 = b[3] * e0.w;
    const float w4 = b[4] * e1.x, w5 = b[5] * e1.y, w6 = b[6] * e1.z, w7 = b[7] * e1.w;
    float h0 = __shfl_down_sync(0xffffffffu, w0, 1);
    float h1 = __shfl_down_sync(0xffffffffu, w1, 1);
    if (lane == 31) { h0 = 0.0f; h1 = 0.0f; }
    h0 *= fD; h1 *= fD;
    b[0] = w0 + w1;
    b[1] = fmaf(a1, w3, w1 + w2);
    b[2] = w2 + w3;
    b[3] = fmaf(a3, w5, w3 + w4);
    b[4] = w4 + w5;
    b[5] = fmaf(a5, w7, w5 + w6);
    b[6] = w6 + w7;
    b[7] = fmaf(a7, h1, w7 + h0);
}

__device__ __forceinline__ int renorm_local(float v[8]) {
    float m = 0.0f;
#pragma unroll
    for (int j = 0; j < 8; j++) m = fmaxf(m, v[j]);
    if (m == 0.0f) return 0x40000000;
    const int e = ((__float_as_int(m) >> 23) & 255) - 127;
    const float f = __int_as_float((unsigned)(127 - e) << 23);
#pragma unroll
    for (int j = 0; j < 8; j++) v[j] *= f;
    return e;
}

__device__ __forceinline__ void renormF(float v[8], int& ex, int lane, float& fD) {
    const int e = renorm_local(v);
    int zi = (e == 0x40000000) ? 1 : 0;
    if (!zi) ex += e;
#pragma unroll
    for (int d = 1; d <= 4; d <<= 1) {
        const int exu = __shfl_up_sync(0xffffffffu, ex, d);
        const int zu = __shfl_up_sync(0xffffffffu, zi, d);
        if (lane >= d && zi) { ex = exu; zi = zu; }
    }
    const int exl = __shfl_up_sync(0xffffffffu, ex, 1);
    int dlt = (lane == 0) ? 0 : (exl - ex);
    dlt = max(-126, min(112, dlt));
    fD = __int_as_float((unsigned)(dlt + 127) << 23);
}
__device__ __forceinline__ void renormFc(float v[8], int& ex, int lane, float& fD) {
    const int e = renorm_local(v);
    if (e != 0x40000000) ex += e;
    const int exl = __shfl_up_sync(0xffffffffu, ex, 1);
    int dlt = (lane == 0) ? 0 : (exl - ex);
    dlt = max(-126, min(112, dlt));
    fD = __int_as_float((unsigned)(dlt + 127) << 23);
}
__device__ __forceinline__ void renormB(float v[8], int& ex, int lane, float& fD) {
    const int e = renorm_local(v);
    int zi = (e == 0x40000000) ? 1 : 0;
    if (!zi) ex += e;
#pragma unroll
    for (int d = 1; d <= 4; d <<= 1) {
        const int exd = __shfl_down_sync(0xffffffffu, ex, d);
        const int zd = __shfl_down_sync(0xffffffffu, zi, d);
        if (lane < 32 - d && zi) { ex = exd; zi = zd; }
    }
    const int exr = __shfl_down_sync(0xffffffffu, ex, 1);
    int dlt = (lane == 31) ? 0 : (exr - ex);
    dlt = max(-126, min(112, dlt));
    fD = __int_as_float((unsigned)(dlt + 127) << 23);
}
__device__ __forceinline__ void renormBc(float v[8], int& ex, int lane, float& fD) {
    const int e = renorm_local(v);
    if (e != 0x40000000) ex += e;
    const int exr = __shfl_down_sync(0xffffffffu, ex, 1);
    int dlt = (lane == 31) ? 0 : (exr - ex);
    dlt = max(-126, min(112, dlt));
    fD = __int_as_float((unsigned)(dlt + 127) << 23);
}

// ============================================================================
// DP kernel (own compilation unit): round-10 bidirectional DP + flag waits.
// Split c = 0.72*len: forward arm c*r matches backward arm's late start
// (t=len-1 produced at ~p*len) + (len-c)*r. Runs CONCURRENTLY with producers
// via stream fork in kernel_launch.
// ============================================================================
__global__ __launch_bounds__(96) void ctc_dp_kernel(
    const int* __restrict__ labels,
    const int* __restrict__ input_lengths,
    const int* __restrict__ label_lengths,
    float* __restrict__ out) {
    const int b = blockIdx.x;
    const int tid = threadIdx.x;
    const int lane = tid & 31, w = tid >> 5;

    __shared__ __align__(16) float eshf[2][BUF];
    __shared__ __align__(16) float eshb[2][BUF];
    __shared__ float sB[256];
    __shared__ int sExB[32];
    __shared__ float s_den, s_corr, s_tot;
    __shared__ int s_ex;

    const int len = input_lengths[b];
    int c = (len * 184) >> 8;                // ~0.72*len
    if (c > len - 2) c = len - 2;
    const char* gbase = (const char*)(g_em + (size_t)b * TT * EW);

    float vF[8];
    int exF = 0;

    if (w == 2) {
        // denominator sums, chasing production per 32-row chunk
        float d = 0.0f, cc = 0.0f;
        for (int base = 0; base < len; base += 32) {
            const int n = min(32, len - base);
            wait_rows(b, base, n);
            if (lane < n) {
                d += g_lse[b * TT + base + lane];
                cc += g_m2[b * TT + base + lane];
            }
        }
        d = warp_sum(d);
        cc = warp_sum(cc);
        if (lane == 0) { s_den = d; s_corr = cc; }
    } else if (w == 0) {
        // ---------------- forward warp ----------------
        eshf[0][8 * EW + lane] = 0.0f; eshf[0][8 * EW + 32 + lane] = 0.0f;
        eshf[1][8 * EW + lane] = 0.0f; eshf[1][8 * EW + 32 + lane] = 0.0f;
        __syncwarp();

        const int s0 = lane * 8;
        float m1 = 0, m3 = 0, m5 = 0, m7 = 0;
        {
            const int* lb = labels + b * LL;
#pragma unroll
            for (int j = 1; j < 8; j += 2) {
                int s = s0 + j;
                float a = 0.0f;
                if (s >= 3 && s <= 200) {
                    int i = s >> 1;
                    a = (lb[i] != lb[i - 1]) ? 1.0f : 0.0f;
                }
                if (j == 1) m1 = a; else if (j == 3) m3 = a;
                else if (j == 5) m5 = a; else m7 = a;
            }
        }

        const unsigned ebase = smem_u32(&eshf[0][0]);
        const int rf = c + 1;                 // rows 0..c
        const int nbf = (rf + 7) >> 3;

#define ISSUE_F(ib) do {                                                         \
        if ((ib) < nbf) {                                                        \
            const char* _s = gbase + (size_t)(ib) * 6656 + lane * 16;            \
            unsigned _d = ebase + (((ib) & 1) * (BUF * 4)) + lane * 16;          \
            _Pragma("unroll")                                                    \
            for (int _k = 0; _k < 13; _k++) cp_async16(_d + _k * 512, _s + _k * 512); \
        }                                                                        \
        asm volatile("cp.async.commit_group;" ::: "memory");                     \
    } while (0)

        wait_rows(b, 0, min(8, rf));
        ISSUE_F(0);
        if (1 < nbf) wait_rows(b, 8, min(8, rf - 8));
        ISSUE_F(1);

#pragma unroll
        for (int j = 0; j < 8; j++) vF[j] = 0.0f;
        float fD = 1.0f;

        for (int ib = 0; ib < nbf; ib++) {
            asm volatile("cp.async.wait_group 1;" ::: "memory");
            const float* base = &eshf[ib & 1][0];
            const float* lp = base + lane * 8;
            const int lim = min(8, rf - ib * 8);
            if (ib == 0) {
                if (lane == 0) { vF[0] = base[0]; vF[1] = base[1]; }
                float4 c0 = *(const float4*)(lp + EW);
                float4 c1 = *(const float4*)(lp + EW + 4);
#pragma unroll
                for (int tt = 1; tt < 8; tt++) {
                    float4 n0 = c0, n1 = c1;
                    if (tt < 7) {
                        n0 = *(const float4*)(lp + (tt + 1) * EW);
                        n1 = *(const float4*)(lp + (tt + 1) * EW + 4);
                    }
                    dpstep32r(vF, c0, c1, lane, m1, m3, m5, m7, fD);
                    c0 = n0; c1 = n1;
                }
            } else if (lim == 8) {
                float4 c0 = *(const float4*)(lp);
                float4 c1 = *(const float4*)(lp + 4);
#pragma unroll
                for (int tt = 0; tt < 8; tt++) {
                    float4 n0 = c0, n1 = c1;
                    if (tt < 7) {
                        n0 = *(const float4*)(lp + (tt + 1) * EW);
                        n1 = *(const float4*)(lp + (tt + 1) * EW + 4);
                    }
                    dpstep32r(vF, c0, c1, lane, m1, m3, m5, m7, fD);
                    c0 = n0; c1 = n1;
                }
            } else {
                for (int tt = 0; tt < lim; tt++) {
                    float4 e0 = *(const float4*)(lp + tt * EW);
                    float4 e1 = *(const float4*)(lp + tt * EW + 4);
                    dpstep32r(vF, e0, e1, lane, m1, m3, m5, m7, fD);
                }
            }
            if (ib < ADOPT_BLKS) renormF(vF, exF, lane, fD);
            else renormFc(vF, exF, lane, fD);
            if (ib + 2 < nbf) wait_rows(b, 8 * (ib + 2), min(8, rf - 8 * (ib + 2)));
            ISSUE_F(ib + 2);
        }
    } else if (w == 1) {
        // ---------------- backward warp ----------------
        eshb[0][8 * EW + lane] = 0.0f; eshb[0][8 * EW + 32 + lane] = 0.0f;
        eshb[1][8 * EW + lane] = 0.0f; eshb[1][8 * EW + 32 + lane] = 0.0f;
        __syncwarp();

        const int s0 = lane * 8;
        float a1 = 0, a3 = 0, a5 = 0, a7 = 0;  // allow(s+2) for odd j
        {
            const int* lb = labels + b * LL;
#pragma unroll
            for (int j = 1; j < 8; j += 2) {
                int sp = s0 + j + 2;
                float a = 0.0f;
                if (sp <= 200) {
                    int i = sp >> 1;
                    a = (lb[i] != lb[i - 1]) ? 1.0f : 0.0f;
                }
                if (j == 1) a1 = a; else if (j == 3) a3 = a;
                else if (j == 5) a5 = a; else a7 = a;
            }
        }

        const unsigned ebase = smem_u32(&eshb[0][0]);
        const int rb = len - 1 - c;               // rows len-1 .. c+1
        const int nbb = (rb + 7) >> 3;

#define ISSUE_B(k) do {                                                          \
        if ((k) < nbb) {                                                         \
            const char* _s = gbase + (size_t)(len - 8 - 8 * (k)) * 832 + lane * 16; \
            unsigned _d = ebase + (((k) & 1) * (BUF * 4)) + lane * 16;           \
            _Pragma("unroll")                                                    \
            for (int _k = 0; _k < 13; _k++) cp_async16(_d + _k * 512, _s + _k * 512); \
        }                                                                        \
        asm volatile("cp.async.commit_group;" ::: "memory");                     \
    } while (0)

        wait_rows(b, len - 8, 8);
        ISSUE_B(0);
        if (1 < nbb) wait_rows(b, len - 16, 8);
        ISSUE_B(1);

        const int end = 2 * label_lengths[b];
        float vB[8];
#pragma unroll
        for (int j = 0; j < 8; j++) {
            int s = s0 + j;
            vB[j] = (s == end || s == end - 1) ? 1.0f : 0.0f;
        }
        int exB = 0;
        float fD = 1.0f;

        for (int k = 0; k < nbb; k++) {
            asm volatile("cp.async.wait_group 1;" ::: "memory");
            const float* base = &eshb[k & 1][0];
            const float* lp = base + lane * 8;
            const int hi = len - 1 - 8 * k;
            const int lim = min(8, hi - c);       // consume rows hi..hi-lim+1
            if (lim == 8) {
                float4 c0 = *(const float4*)(lp + 7 * EW);
                float4 c1 = *(const float4*)(lp + 7 * EW + 4);
#pragma unroll
                for (int tt = 0; tt < 8; tt++) {
                    float4 n0 = c0, n1 = c1;
                    if (tt < 7) {
                        n0 = *(const float4*)(lp + (6 - tt) * EW);
                        n1 = *(const float4*)(lp + (6 - tt) * EW + 4);
                    }
                    bstep32r(vB, c0, c1, lane, a1, a3, a5, a7, fD);
                    c0 = n0; c1 = n1;
                }
            } else {
                for (int tt = 0; tt < lim; tt++) {
                    float4 e0 = *(const float4*)(lp + (7 - tt) * EW);
                    float4 e1 = *(const float4*)(lp + (7 - tt) * EW + 4);
                    bstep32r(vB, e0, e1, lane, a1, a3, a5, a7, fD);
                }
            }
            if (k < ADOPT_BLKS) renormB(vB, exB, lane, fD);
            else renormBc(vB, exB, lane, fD);
            if (k + 2 < nbb) wait_rows(b, len - 8 - 8 * (k + 2), 8);
            ISSUE_B(k + 2);
        }

#pragma unroll
        for (int j = 0; j < 8; j++) sB[s0 + j] = vB[j];
        sExB[lane] = exB;
    }
    __syncthreads();

    if (w == 0) {
        float p = 0.0f;
        const int s0 = lane * 8;
#pragma unroll
        for (int j = 0; j < 8; j++) p += vF[j] * sB[s0 + j];
        const int e = exF + sExB[lane];
        int exv = (p > 0.0f) ? e : (int)0xC0000000;
        int exm = exv;
#pragma unroll
        for (int o = 16; o; o >>= 1) exm = max(exm, __shfl_xor_sync(0xffffffffu, exm, o));
        float a = (p > 0.0f) ? p * exp2f((float)(e - exm)) : 0.0f;
        a = warp_sum(a);
        if (lane == 0) { s_tot = a; s_ex = exm; }
    }
    __syncthreads();
    if (tid == 0) {
        const double lognum = log((double)s_tot) + (double)s_ex * LN2D + (double)s_corr;
        const float nll = -(float)lognum;
        g_cost[b] = s_den - (1.0f + LAMB) * nll;

        __threadfence();
        const int arrived = atomicAdd(&g_cnt, 1);
        if (arrived == BB - 1) {
            float s = 0.0f;
#pragma unroll
            for (int i = 0; i < BB; i++) s += g_cost[i];
            out[0] = s / (float)BB;
            g_cnt = 0;  // reset for next replay
        }
    }
}

extern "C" void kernel_launch(void* const* d_in, const int* in_sizes, int n_in,
                              void* d_out, int out_size) {
    const float* logits = (const float*)d_in[0];
    const int* labels = (const int*)d_in[1];
    const int* input_lengths = (const int*)d_in[2];
    const int* label_lengths = (const int*)d_in[3];
    float* out = (float*)d_out;

    // Fork-join: producers on s2 run CONCURRENTLY with the DP kernel on the
    // null stream (DP synchronizes via per-row flags). Streams/events are
    // host-side objects (no device memory); created per call, few calls total.
    cudaStream_t s2;
    cudaStreamCreateWithFlags(&s2, cudaStreamNonBlocking);
    cudaEvent_t ef, ej;
    cudaEventCreateWithFlags(&ef, cudaEventDisableTiming);
    cudaEventCreateWithFlags(&ej, cudaEventDisableTiming);

    reset_kernel<<<(BB * TT + 255) / 256, 256>>>();
    cudaEventRecord(ef, 0);
    cudaStreamWaitEvent(s2, ef, 0);

    producer_kernel<<<BB * TT, 256, 0, s2>>>(logits, labels, input_lengths);
    ctc_dp_kernel<<<BB, 96>>>(labels, input_lengths, label_lengths, out);

    cudaEventRecord(ej, s2);
    cudaStreamWaitEvent(0, ej, 0);
}

// round 13
// speedup vs baseline: 1.8993x; 1.4772x over previous
#include <cuda_runtime.h>
#include <cuda_bf16.h>

#define BB 16
#define TT 800
#define VV 4000
#define LL 100
#define SS 201        // 2L+1 states
#define EW 208        // emission row stride in smem (floats)
#define BLK 12        // rows per pipeline block (2 rows per producer warp)
#define FBUFN (BLK * EW + 64)  // buffer floats incl. over-read pad
#define NEGV (-1e30f)
#define LAMB 0.1f
#define LN2D 0.6931471805599453094
#define ADOPT_BLKS 10 // full renorm (zero-lane adoption) while frontier expands

// Scratch (__device__ globals per allocation-free rule)
__device__ float g_lse[BB * TT];
__device__ float g_den[BB];
__device__ float g_cost[BB];
__device__ int g_acnt[BB];   // kernel-A per-batch arrival counters
__device__ int g_dflag[BB];  // den-ready flags
__device__ int g_cnt;        // finalize counter

__inline__ __device__ float warp_max(float v) {
#pragma unroll
    for (int o = 16; o; o >>= 1) v = fmaxf(v, __shfl_xor_sync(0xffffffffu, v, o));
    return v;
}
__inline__ __device__ float warp_sum(float v) {
#pragma unroll
    for (int o = 16; o; o >>= 1) v += __shfl_xor_sync(0xffffffffu, v, o);
    return v;
}
__device__ __forceinline__ int ld_acq(const int* p) {
    int v;
    asm volatile("ld.global.acquire.gpu.b32 %0, [%1];" : "=r"(v) : "l"(p) : "memory");
    return v;
}

// ============================================================================
// Kernel 0: reset consumed state (graph-replay determinism)
// ============================================================================
__global__ void reset_kernel() {
    const int i = threadIdx.x;
    if (i < BB) { g_acnt[i] = 0; g_dflag[i] = 0; }
    if (i == 0) g_cnt = 0;
}

// ============================================================================
// Kernel A: per-(b,t) logsumexp over V (single HBM pass). Last-arriving CTA
// of each batch computes den[b] = sum_{t<len} lse (deterministic fixed-order
// warp sum) and releases the batch flag. Completely independent of kernel B
// until B's final scalar read.
// ============================================================================
__global__ __launch_bounds__(256) void lse_den_kernel(
    const float* __restrict__ logits, const int* __restrict__ input_lengths) {
    const int lin = blockIdx.x;
    const int t = lin >> 4, b = lin & 15;   // t-major: all batches advance together
    const int len = __ldg(input_lengths + b);
    if (t >= len) return;

    const int bt = b * TT + t;
    const float* __restrict__ row = logits + (size_t)bt * VV;
    const int tid = threadIdx.x;
    const int lane = tid & 31, wid = tid >> 5;

    float s = 0.0f;
#pragma unroll
    for (int i = 0; i < 4; i++) {
        int idx = tid + i * 256;
        if (idx < VV / 4) {
            float4 v = reinterpret_cast<const float4*>(row)[idx];
            s += __expf(v.x) + __expf(v.y) + __expf(v.z) + __expf(v.w);
        }
    }
    __shared__ float ssum[8];
    __shared__ int slast;
    s = warp_sum(s);
    if (lane == 0) ssum[wid] = s;
    __syncthreads();
    s = ssum[0];
#pragma unroll
    for (int i = 1; i < 8; i++) s += ssum[i];
    if (tid == 0) g_lse[bt] = __logf(s);

    __threadfence();
    __syncthreads();
    if (tid == 0) slast = (atomicAdd(&g_acnt[b], 1) == len - 1) ? 1 : 0;
    __syncthreads();
    if (slast && tid < 32) {
        float d = 0.0f;
        for (int tt = lane; tt < len; tt += 32) d += g_lse[b * TT + tt];
        d = warp_sum(d);
        if (lane == 0) {
            g_den[b] = d;
            __threadfence();
            atomicExch(&g_dflag[b], 1);
        }
    }
}

// ============================================================================
// DP machinery (validated rounds 5-10)
// ============================================================================
__device__ __forceinline__ void dpstep32(float v[8], const float* __restrict__ erow,
                                         int lane, float m1, float m3, float m5,
                                         float m7, float fD) {
    const float4 e0 = *reinterpret_cast<const float4*>(erow + lane * 8);
    const float4 e1 = *reinterpret_cast<const float4*>(erow + lane * 8 + 4);
    float hi1 = __shfl_up_sync(0xffffffffu, v[7], 1);
    const float hiX = (lane == 0) ? 0.0f : hi1 * fD;
    const float u7 = fmaf(m7, v[5], v[6]);
    const float u5 = fmaf(m5, v[3], v[4]);
    const float u3 = fmaf(m3, v[1], v[2]);
    const float u1 = fmaf(m1, hiX, v[0]);
    v[7] = fmaf(v[7], e1.w, u7 * e1.w);
    v[6] = fmaf(v[6], e1.z, v[5] * e1.z);
    v[5] = fmaf(v[5], e1.y, u5 * e1.y);
    v[4] = fmaf(v[4], e1.x, v[3] * e1.x);
    v[3] = fmaf(v[3], e0.w, u3 * e0.w);
    v[2] = fmaf(v[2], e0.z, v[1] * e0.z);
    v[1] = fmaf(v[1], e0.y, u1 * e0.y);
    v[0] = fmaf(v[0], e0.x, hiX * e0.x);
}

__device__ __forceinline__ void bstep32(float b[8], const float* __restrict__ erow,
                                        int lane, float a1, float a3, float a5,
                                        float a7, float fD) {
    const float4 e0 = *reinterpret_cast<const float4*>(erow + lane * 8);
    const float4 e1 = *reinterpret_cast<const float4*>(erow + lane * 8 + 4);
    const float w0 = b[0] * e0.x, w1 = b[1] * e0.y, w2 = b[2] * e0.z, w3 = b[3] * e0.w;
    const float w4 = b[4] * e1.x, w5 = b[5] * e1.y, w6 = b[6] * e1.z, w7 = b[7] * e1.w;
    float h0 = __shfl_down_sync(0xffffffffu, w0, 1);
    float h1 = __shfl_down_sync(0xffffffffu, w1, 1);
    if (lane == 31) { h0 = 0.0f; h1 = 0.0f; }
    h0 *= fD; h1 *= fD;
    b[0] = w0 + w1;
    b[1] = fmaf(a1, w3, w1 + w2);
    b[2] = w2 + w3;
    b[3] = fmaf(a3, w5, w3 + w4);
    b[4] = w4 + w5;
    b[5] = fmaf(a5, w7, w5 + w6);
    b[6] = w6 + w7;
    b[7] = fmaf(a7, h1, w7 + h0);
}

__device__ __forceinline__ int renorm_local(float v[8]) {
    float m = 0.0f;
#pragma unroll
    for (int j = 0; j < 8; j++) m = fmaxf(m, v[j]);
    if (m == 0.0f) return 0x40000000;
    const int e = ((__float_as_int(m) >> 23) & 255) - 127;
    const float f = __int_as_float((unsigned)(127 - e) << 23);
#pragma unroll
    for (int j = 0; j < 8; j++) v[j] *= f;
    return e;
}
__device__ __forceinline__ void renormF(float v[8], int& ex, int lane, float& fD) {
    const int e = renorm_local(v);
    int zi = (e == 0x40000000) ? 1 : 0;
    if (!zi) ex += e;
#pragma unroll
    for (int d = 1; d <= 4; d <<= 1) {
        const int exu = __shfl_up_sync(0xffffffffu, ex, d);
        const int zu = __shfl_up_sync(0xffffffffu, zi, d);
        if (lane >= d && zi) { ex = exu; zi = zu; }
    }
    const int exl = __shfl_up_sync(0xffffffffu, ex, 1);
    int dlt = (lane == 0) ? 0 : (exl - ex);
    dlt = max(-126, min(112, dlt));
    fD = __int_as_float((unsigned)(dlt + 127) << 23);
}
__device__ __forceinline__ void renormFc(float v[8], int& ex, int lane, float& fD) {
    const int e = renorm_local(v);
    if (e != 0x40000000) ex += e;
    const int exl = __shfl_up_sync(0xffffffffu, ex, 1);
    int dlt = (lane == 0) ? 0 : (exl - ex);
    dlt = max(-126, min(112, dlt));
    fD = __int_as_float((unsigned)(dlt + 127) << 23);
}
__device__ __forceinline__ void renormB(float v[8], int& ex, int lane, float& fD) {
    const int e = renorm_local(v);
    int zi = (e == 0x40000000) ? 1 : 0;
    if (!zi) ex += e;
#pragma unroll
    for (int d = 1; d <= 4; d <<= 1) {
        const int exd = __shfl_down_sync(0xffffffffu, ex, d);
        const int zd = __shfl_down_sync(0xffffffffu, zi, d);
        if (lane < 32 - d && zi) { ex = exd; zi = zd; }
    }
    const int exr = __shfl_down_sync(0xffffffffu, ex, 1);
    int dlt = (lane == 31) ? 0 : (exr - ex);
    dlt = max(-126, min(112, dlt));
    fD = __int_as_float((unsigned)(dlt + 127) << 23);
}
__device__ __forceinline__ void renormBc(float v[8], int& ex, int lane, float& fD) {
    const int e = renorm_local(v);
    if (e != 0x40000000) ex += e;
    const int exr = __shfl_down_sync(0xffffffffu, ex, 1);
    int dlt = (lane == 31) ? 0 : (exr - ex);
    dlt = max(-126, min(112, dlt));
    fD = __int_as_float((unsigned)(dlt + 127) << 23);
}

// ============================================================================
// Kernel B: self-sufficient bidirectional CTC DP. One CTA (15 warps) per
// batch. Producer warps gather the 201 needed logits per row straight from
// global memory, compute gm + linear emissions into double-buffered smem.
//   warp 0:      forward consumer (rows 0..c)        [barrier 1 group]
//   warps 3..8:  front producers (2 rows/warp/block) [barrier 1 group]
//   warp 1:      backward consumer (rows len-1..c+1) [barrier 2 group]
//   warps 9..14: back producers                      [barrier 2 group]
//   warp 2: idle. Final: Total = sum_s aF[s]*aB[s]; den read from kernel A.
// ============================================================================
__global__ __launch_bounds__(480, 1) void ctc_dp_kernel(
    const float* __restrict__ logits,
    const int* __restrict__ labels,
    const int* __restrict__ input_lengths,
    const int* __restrict__ label_lengths,
    float* __restrict__ out) {
    const int b = blockIdx.x;
    const int tid = threadIdx.x;
    const int lane = tid & 31, wid = tid >> 5;

    __shared__ __align__(16) float fbuf[2][FBUFN];
    __shared__ __align__(16) float bbuf[2][FBUFN];
    __shared__ float sB[256];
    __shared__ int sExB[32];
    __shared__ float gsum[16];
    __shared__ float s_tot;
    __shared__ int s_ex;

    const int len = input_lengths[b];
    const int c = (len - 1) >> 1;
    const int rf = c + 1;                 // front rows 0..c
    const int nbf = (rf + BLK - 1) / BLK;
    const int nbb = ((len - 1 - c) + BLK - 1) / BLK;
    const float* __restrict__ lgb = logits + (size_t)b * TT * VV;
    const int* __restrict__ lb = labels + b * LL;

    // zero all buffers (stale/uninit smem must never be NaN for over-reads)
    for (int i = tid; i < FBUFN; i += 480) {
        fbuf[0][i] = 0.0f; fbuf[1][i] = 0.0f;
        bbuf[0][i] = 0.0f; bbuf[1][i] = 0.0f;
    }
    if (tid < 16) gsum[tid] = 0.0f;
    __syncthreads();

    float vF[8];
    int exF = 0;

    if (wid == 0) {
        // ---------------- forward consumer ----------------
        const int s0 = lane * 8;
        float m1 = 0, m3 = 0, m5 = 0, m7 = 0;
#pragma unroll
        for (int j = 1; j < 8; j += 2) {
            int s = s0 + j;
            float a = 0.0f;
            if (s >= 3 && s <= 200) {
                int i = s >> 1;
                a = (lb[i] != lb[i - 1]) ? 1.0f : 0.0f;
            }
            if (j == 1) m1 = a; else if (j == 3) m3 = a;
            else if (j == 5) m5 = a; else m7 = a;
        }
#pragma unroll
        for (int j = 0; j < 8; j++) vF[j] = 0.0f;
        float fD = 1.0f;

        for (int k = 0; k < nbf; k++) {
            asm volatile("bar.sync 1, 224;" ::: "memory");  // block k filled
            const float* basep = &fbuf[k & 1][0];
            const int lim = min(BLK, rf - k * BLK);
            if (k == 0) {
                if (lane == 0) { vF[0] = basep[0]; vF[1] = basep[1]; }
#pragma unroll
                for (int tt = 1; tt < BLK; tt++)   // block 0 always full
                    dpstep32(vF, basep + tt * EW, lane, m1, m3, m5, m7, fD);
            } else if (lim == BLK) {
#pragma unroll
                for (int tt = 0; tt < BLK; tt++)
                    dpstep32(vF, basep + tt * EW, lane, m1, m3, m5, m7, fD);
            } else {
                for (int tt = 0; tt < lim; tt++)
                    dpstep32(vF, basep + tt * EW, lane, m1, m3, m5, m7, fD);
            }
            if (k < ADOPT_BLKS) renormF(vF, exF, lane, fD);
            else renormFc(vF, exF, lane, fD);
        }
    } else if (wid == 1) {
        // ---------------- backward consumer ----------------
        const int s0 = lane * 8;
        float a1 = 0, a3 = 0, a5 = 0, a7 = 0;
#pragma unroll
        for (int j = 1; j < 8; j += 2) {
            int sp = s0 + j + 2;
            float a = 0.0f;
            if (sp <= 200) {
                int i = sp >> 1;
                a = (lb[i] != lb[i - 1]) ? 1.0f : 0.0f;
            }
            if (j == 1) a1 = a; else if (j == 3) a3 = a;
            else if (j == 5) a5 = a; else a7 = a;
        }
        const int end = 2 * label_lengths[b];
        float vB[8];
#pragma unroll
        for (int j = 0; j < 8; j++) {
            int s = s0 + j;
            vB[j] = (s == end || s == end - 1) ? 1.0f : 0.0f;
        }
        int exB = 0;
        float fD = 1.0f;

        for (int k = 0; k < nbb; k++) {
            asm volatile("bar.sync 2, 224;" ::: "memory");
            const float* basep = &bbuf[k & 1][0];
            const int hi = len - 1 - BLK * k;
            const int lim = min(BLK, hi - c);     // rows stored descending: row i <-> t=hi-i
            if (lim == BLK) {
#pragma unroll
                for (int tt = 0; tt < BLK; tt++)
                    bstep32(vB, basep + tt * EW, lane, a1, a3, a5, a7, fD);
            } else {
                for (int tt = 0; tt < lim; tt++)
                    bstep32(vB, basep + tt * EW, lane, a1, a3, a5, a7, fD);
            }
            if (k < ADOPT_BLKS) renormB(vB, exB, lane, fD);
            else renormBc(vB, exB, lane, fD);
        }
#pragma unroll
        for (int j = 0; j < 8; j++) sB[s0 + j] = vB[j];
        sExB[lane] = exB;
    } else if (wid >= 3) {
        // ---------------- producers ----------------
        const bool front = (wid < 9);
        const int p = front ? (wid - 3) : (wid - 9);   // 0..5
        // per-lane static column byte-layout: s = lane + 32q
        int col[7];
#pragma unroll
        for (int q = 0; q < 7; q++) {
            int s = lane + 32 * q;
            col[q] = (s <= 200) ? ((s & 1) ? lb[s >> 1] : 0) : 0;
        }
        const int nb = front ? nbf : nbb;
        const int barid = front ? 1 : 2;
        float gacc = 0.0f;

        for (int k = 0; k < nb; k++) {
            float* dst = front ? &fbuf[k & 1][0] : &bbuf[k & 1][0];
#pragma unroll
            for (int ii = 0; ii < 2; ii++) {
                const int i = p * 2 + ii;            // row within block
                const int t = front ? (k * BLK + i) : (len - 1 - BLK * k - i);
                const bool valid = front ? (t < rf) : (t > c);
                if (valid) {
                    const float* rp = lgb + (size_t)t * VV;
                    float x[7];
                    float mx = NEGV;
#pragma unroll
                    for (int q = 0; q < 6; q++) {
                        x[q] = __ldg(rp + col[q]);
                        mx = fmaxf(mx, x[q]);
                    }
                    if (lane <= 8) {                 // q=6: s=192+lane <= 200
                        x[6] = __ldg(rp + col[6]);
                        mx = fmaxf(mx, x[6]);
                    }
                    mx = warp_max(mx);
                    float* dr = dst + i * EW;
#pragma unroll
                    for (int q = 0; q < 6; q++)
                        dr[lane + 32 * q] = __expf(x[q] - mx);
                    if (lane <= 15)                  // slots 192..207: valid or 0-pad
                        dr[192 + lane] = (lane <= 8) ? __expf(x[6] - mx) : 0.0f;
                    if (lane == 0) gacc += mx;       // sum of gm (deterministic order)
                }
            }
            if (barid == 1) asm volatile("bar.sync 1, 224;" ::: "memory");
            else            asm volatile("bar.sync 2, 224;" ::: "memory");
        }
        if (lane == 0) gsum[wid] = gacc;
    }
    __syncthreads();

    if (wid == 0) {
        // combine: Total = sum_s alpha_c[s] * beta_c[s]
        float pr = 0.0f;
        const int s0 = lane * 8;
#pragma unroll
        for (int j = 0; j < 8; j++) pr += vF[j] * sB[s0 + j];
        const int e = exF + sExB[lane];
        int exv = (pr > 0.0f) ? e : (int)0xC0000000;
        int exm = exv;
#pragma unroll
        for (int o = 16; o; o >>= 1) exm = max(exm, __shfl_xor_sync(0xffffffffu, exm, o));
        float a = (pr > 0.0f) ? pr * exp2f((float)(e - exm)) : 0.0f;
        a = warp_sum(a);
        if (lane == 0) { s_tot = a; s_ex = exm; }
        __syncwarp();

        if (tid == 0) {
            float gmt = 0.0f;
#pragma unroll
            for (int i = 3; i < 15; i++) gmt += gsum[i];  // fixed order
            // wait for kernel A's den (ready long before in practice)
            while (ld_acq(&g_dflag[b]) == 0) __nanosleep(256);
            const float den = g_den[b];
            const float corr = gmt - den;                 // = sum(gm - lse)
            const double lognum =
                log((double)s_tot) + (double)s_ex * LN2D + (double)corr;
            const float nll = -(float)lognum;
            g_cost[b] = den - (1.0f + LAMB) * nll;

            __threadfence();
            const int arrived = atomicAdd(&g_cnt, 1);
            if (arrived == BB - 1) {
                float s = 0.0f;
#pragma unroll
                for (int i = 0; i < BB; i++) s += g_cost[i];
                out[0] = s / (float)BB;
                g_cnt = 0;  // reset for next replay
            }
        }
    }
}

extern "C" void kernel_launch(void* const* d_in, const int* in_sizes, int n_in,
                              void* d_out, int out_size) {
    const float* logits = (const float*)d_in[0];
    const int* labels = (const int*)d_in[1];
    const int* input_lengths = (const int*)d_in[2];
    const int* label_lengths = (const int*)d_in[3];
    float* out = (float*)d_out;

    // A and B are independent (B reads A's output only via the tiny den flag
    // at its very end) -> run them on forked streams; any serialization order
    // also completes correctly.
    cudaStream_t s2;
    cudaStreamCreateWithFlags(&s2, cudaStreamNonBlocking);
    cudaEvent_t ef, ej;
    cudaEventCreateWithFlags(&ef, cudaEventDisableTiming);
    cudaEventCreateWithFlags(&ej, cudaEventDisableTiming);

    reset_kernel<<<1, 64>>>();
    cudaEventRecord(ef, 0);
    cudaStreamWaitEvent(s2, ef, 0);

    lse_den_kernel<<<BB * TT, 256, 0, s2>>>(logits, input_lengths);
    ctc_dp_kernel<<<BB, 480>>>(logits, labels, input_lengths, label_lengths, out);

    cudaEventRecord(ej, s2);
    cudaStreamWaitEvent(0, ej, 0);
}

// round 14
// speedup vs baseline: 3.3360x; 1.7564x over previous
#include <cuda_runtime.h>
#include <cuda_bf16.h>

#define BB 16
#define TT 800
#define VV 4000
#define LL 100
#define SS 201        // 2L+1 states
#define EW 208        // emission row stride (floats): 832B rows
#define BUF 1728      // shared buffer floats: 8*EW + 64 pad
#define NEGV (-1e30f)
#define LAMB 0.1f
#define LN2D 0.6931471805599453094
#define ADOPT_BLKS 14 // full renorm (zero-lane adoption) for first 14 blocks

// Scratch (__device__ globals per allocation-free rule)
__device__ float g_lse[BB * TT];
__device__ float g_m2[BB * TT];
__device__ __align__(16) float g_em[(size_t)BB * TT * EW];  // 10.6 MB
__device__ float g_cost[BB];
__device__ int g_cnt;  // arrival counter (self-resetting -> graph-replay safe)

__inline__ __device__ float warp_max(float v) {
#pragma unroll
    for (int o = 16; o; o >>= 1) v = fmaxf(v, __shfl_xor_sync(0xffffffffu, v, o));
    return v;
}
__inline__ __device__ float warp_sum(float v) {
#pragma unroll
    for (int o = 16; o; o >>= 1) v += __shfl_xor_sync(0xffffffffu, v, o);
    return v;
}
__device__ __forceinline__ unsigned smem_u32(const void* p) {
    return (unsigned)__cvta_generic_to_shared(p);
}
__device__ __forceinline__ void cp_async16(unsigned dst, const void* src) {
    asm volatile("cp.async.cg.shared.global [%0], [%1], 16;" :: "r"(dst), "l"(src) : "memory");
}

// ============================================================================
// Kernel 1: per-(b,t) single-pass sum-of-exp lse + gather of the 201
// extended-state logits -> max-normalized LINEAR fp32 emissions.
// Rows with t >= input_lengths[b] are skipped entirely.
// ============================================================================
__global__ __launch_bounds__(256) void lse_gather_kernel(
    const float* __restrict__ logits, const int* __restrict__ labels,
    const int* __restrict__ input_lengths) {
    const int t = blockIdx.x, b = blockIdx.y;
    if (t >= __ldg(input_lengths + b)) return;

    const int bt = b * TT + t;
    const float* __restrict__ row = logits + (size_t)bt * VV;
    const int tid = threadIdx.x;
    const int lane = tid & 31, wid = tid >> 5;

    float s = 0.0f;
#pragma unroll
    for (int i = 0; i < 4; i++) {
        int idx = tid + i * 256;
        if (idx < VV / 4) {
            float4 v = reinterpret_cast<const float4*>(row)[idx];
            s += __expf(v.x) + __expf(v.y) + __expf(v.z) + __expf(v.w);
        }
    }
    __shared__ float ssum[8], sgm[8];
    s = warp_sum(s);
    if (lane == 0) ssum[wid] = s;

    float val = NEGV;
    if (tid <= 200) {
        int vv = (tid & 1) ? labels[b * LL + (tid >> 1)] : 0;
        val = __ldg(row + vv);
    }
    float gm = warp_max(val);
    if (lane == 0) sgm[wid] = gm;
    __syncthreads();

    s = ssum[0];
    gm = sgm[0];
#pragma unroll
    for (int i = 1; i < 8; i++) { s += ssum[i]; gm = fmaxf(gm, sgm[i]); }
    const float lse = __logf(s);

    if (tid < EW)
        g_em[(size_t)bt * EW + tid] = (tid <= 200) ? __expf(val - gm) : 0.0f;
    if (tid == 0) {
        g_lse[bt] = lse;
        g_m2[bt] = gm - lse;
    }
}

// ============================================================================
// Kernel 2: bidirectional CTC DP, chains on SEPARATE warps/SMSPs, with BOTH
// the emission loads AND the halo shuffles software-pipelined: the shfl for
// step t+1 is issued immediately after v[7]/b[0..1] update at step t, so its
// 26-cycle latency hides under the next step's issue stream.
//   warp 0: forward alpha t=0..c ; warp 1: backward beta t=len-1..c+1
//   warp 2: costs_den = sum lse, corr = sum m2
// ============================================================================
// forward step: hi = raw left-lane v[7] (pre-shuffled); updates v, re-shuffles.
__device__ __forceinline__ void dpstep32p(float v[8], float4 e0, float4 e1,
                                          int lane, float m1, float m3, float m5,
                                          float m7, float fD, float& hi) {
    const float hiX = (lane == 0) ? 0.0f : hi * fD;
    const float u7 = fmaf(m7, v[5], v[6]);
    const float u5 = fmaf(m5, v[3], v[4]);
    const float u3 = fmaf(m3, v[1], v[2]);
    const float u1 = fmaf(m1, hiX, v[0]);
    v[7] = fmaf(v[7], e1.w, u7 * e1.w);
    v[6] = fmaf(v[6], e1.z, v[5] * e1.z);
    v[5] = fmaf(v[5], e1.y, u5 * e1.y);
    v[4] = fmaf(v[4], e1.x, v[3] * e1.x);
    v[3] = fmaf(v[3], e0.w, u3 * e0.w);
    v[2] = fmaf(v[2], e0.z, v[1] * e0.z);
    v[1] = fmaf(v[1], e0.y, u1 * e0.y);
    v[0] = fmaf(v[0], e0.x, hiX * e0.x);
    hi = __shfl_up_sync(0xffffffffu, v[7], 1);  // for NEXT step (latency hidden)
}

// backward step: h0p/h1p = raw right-lane b[0],b[1] (pre-shuffled);
// e8/e9 = right lane's e0.x/e0.y loaded from smem by THIS lane.
__device__ __forceinline__ void bstep32p(float b[8], float4 e0, float4 e1,
                                         float e8, float e9, int lane,
                                         float a1, float a3, float a5, float a7,
                                         float fD, float& h0p, float& h1p) {
    // right lane's w0/w1, reproduced bit-exactly: b0r*e0r with identical inputs
    float h0 = (lane == 31) ? 0.0f : h0p * e8;
    float h1 = (lane == 31) ? 0.0f : h1p * e9;
    const float w0 = b[0] * e0.x, w1 = b[1] * e0.y, w2 = b[2] * e0.z, w3 = b[3] * e0.w;
    const float w4 = b[4] * e1.x, w5 = b[5] * e1.y, w6 = b[6] * e1.z, w7 = b[7] * e1.w;
    h0 *= fD; h1 *= fD;
    b[0] = w0 + w1;
    b[1] = fmaf(a1, w3, w1 + w2);
    b[2] = w2 + w3;
    b[3] = fmaf(a3, w5, w3 + w4);
    b[4] = w4 + w5;
    b[5] = fmaf(a5, w7, w5 + w6);
    b[6] = w6 + w7;
    b[7] = fmaf(a7, h1, w7 + h0);
    h0p = __shfl_down_sync(0xffffffffu, b[0], 1);  // for NEXT step
    h1p = __shfl_down_sync(0xffffffffu, b[1], 1);
}

__device__ __forceinline__ int renorm_local(float v[8]) {
    float m = 0.0f;
#pragma unroll
    for (int j = 0; j < 8; j++) m = fmaxf(m, v[j]);
    if (m == 0.0f) return 0x40000000;
    const int e = ((__float_as_int(m) >> 23) & 255) - 127;
    const float f = __int_as_float((unsigned)(127 - e) << 23);
#pragma unroll
    for (int j = 0; j < 8; j++) v[j] *= f;
    return e;
}
__device__ __forceinline__ void renormF(float v[8], int& ex, int lane, float& fD) {
    const int e = renorm_local(v);
    int zi = (e == 0x40000000) ? 1 : 0;
    if (!zi) ex += e;
#pragma unroll
    for (int d = 1; d <= 4; d <<= 1) {
        const int exu = __shfl_up_sync(0xffffffffu, ex, d);
        const int zu = __shfl_up_sync(0xffffffffu, zi, d);
        if (lane >= d && zi) { ex = exu; zi = zu; }
    }
    const int exl = __shfl_up_sync(0xffffffffu, ex, 1);
    int dlt = (lane == 0) ? 0 : (exl - ex);
    dlt = max(-126, min(112, dlt));
    fD = __int_as_float((unsigned)(dlt + 127) << 23);
}
__device__ __forceinline__ void renormFc(float v[8], int& ex, int lane, float& fD) {
    const int e = renorm_local(v);
    if (e != 0x40000000) ex += e;
    const int exl = __shfl_up_sync(0xffffffffu, ex, 1);
    int dlt = (lane == 0) ? 0 : (exl - ex);
    dlt = max(-126, min(112, dlt));
    fD = __int_as_float((unsigned)(dlt + 127) << 23);
}
__device__ __forceinline__ void renormB(float v[8], int& ex, int lane, float& fD) {
    const int e = renorm_local(v);
    int zi = (e == 0x40000000) ? 1 : 0;
    if (!zi) ex += e;
#pragma unroll
    for (int d = 1; d <= 4; d <<= 1) {
        const int exd = __shfl_down_sync(0xffffffffu, ex, d);
        const int zd = __shfl_down_sync(0xffffffffu, zi, d);
        if (lane < 32 - d && zi) { ex = exd; zi = zd; }
    }
    const int exr = __shfl_down_sync(0xffffffffu, ex, 1);
    int dlt = (lane == 31) ? 0 : (exr - ex);
    dlt = max(-126, min(112, dlt));
    fD = __int_as_float((unsigned)(dlt + 127) << 23);
}
__device__ __forceinline__ void renormBc(float v[8], int& ex, int lane, float& fD) {
    const int e = renorm_local(v);
    if (e != 0x40000000) ex += e;
    const int exr = __shfl_down_sync(0xffffffffu, ex, 1);
    int dlt = (lane == 31) ? 0 : (exr - ex);
    dlt = max(-126, min(112, dlt));
    fD = __int_as_float((unsigned)(dlt + 127) << 23);
}

__global__ __launch_bounds__(96) void ctc_dp_kernel(
    const int* __restrict__ labels,
    const int* __restrict__ input_lengths,
    const int* __restrict__ label_lengths,
    float* __restrict__ out) {
    const int b = blockIdx.x;
    const int tid = threadIdx.x;
    const int lane = tid & 31, w = tid >> 5;

    __shared__ __align__(16) float eshf[2][BUF];
    __shared__ __align__(16) float eshb[2][BUF];
    __shared__ float sB[256];
    __shared__ int sExB[32];
    __shared__ float s_den, s_corr, s_tot;
    __shared__ int s_ex;

    const int len = input_lengths[b];
    const int c = (len - 1) >> 1;            // forward covers 0..c
    const char* gbase = (const char*)(g_em + (size_t)b * TT * EW);

    float vF[8];
    int exF = 0;

    if (w == 2) {
        float d = 0.0f, cc = 0.0f;
        for (int t = lane; t < len; t += 32) {
            d += g_lse[b * TT + t];
            cc += g_m2[b * TT + t];
        }
        d = warp_sum(d);
        cc = warp_sum(cc);
        if (lane == 0) { s_den = d; s_corr = cc; }
    } else if (w == 0) {
        // ---------------- forward warp ----------------
        eshf[0][8 * EW + lane] = 0.0f; eshf[0][8 * EW + 32 + lane] = 0.0f;
        eshf[1][8 * EW + lane] = 0.0f; eshf[1][8 * EW + 32 + lane] = 0.0f;
        __syncwarp();

        const int s0 = lane * 8;
        float m1 = 0, m3 = 0, m5 = 0, m7 = 0;
        {
            const int* lb = labels + b * LL;
#pragma unroll
            for (int j = 1; j < 8; j += 2) {
                int s = s0 + j;
                float a = 0.0f;
                if (s >= 3 && s <= 200) {
                    int i = s >> 1;
                    a = (lb[i] != lb[i - 1]) ? 1.0f : 0.0f;
                }
                if (j == 1) m1 = a; else if (j == 3) m3 = a;
                else if (j == 5) m5 = a; else m7 = a;
            }
        }

        const unsigned ebase = smem_u32(&eshf[0][0]);
        const int rf = c + 1;                 // rows 0..c
        const int nbf = (rf + 7) >> 3;

#define ISSUE_F(ib) do {                                                         \
        if ((ib) < nbf) {                                                        \
            const char* _s = gbase + (size_t)(ib) * 6656 + lane * 16;            \
            unsigned _d = ebase + (((ib) & 1) * (BUF * 4)) + lane * 16;          \
            _Pragma("unroll")                                                    \
            for (int _k = 0; _k < 13; _k++) cp_async16(_d + _k * 512, _s + _k * 512); \
        }                                                                        \
        asm volatile("cp.async.commit_group;" ::: "memory");                     \
    } while (0)

        ISSUE_F(0);
        ISSUE_F(1);

#pragma unroll
        for (int j = 0; j < 8; j++) vF[j] = 0.0f;
        float fD = 1.0f;
        float hi = 0.0f;   // left-lane v[7], pre-shuffled (all zero at t=0)

        for (int ib = 0; ib < nbf; ib++) {
            asm volatile("cp.async.wait_group 1;" ::: "memory");
            const float* base = &eshf[ib & 1][0];
            const float* lp = base + lane * 8;
            const int lim = min(8, rf - ib * 8);
            if (ib == 0) {
                if (lane == 0) { vF[0] = base[0]; vF[1] = base[1]; }
                hi = __shfl_up_sync(0xffffffffu, vF[7], 1);
                float4 c0 = *(const float4*)(lp + EW);
                float4 c1 = *(const float4*)(lp + EW + 4);
#pragma unroll
                for (int tt = 1; tt < 8; tt++) {
                    float4 n0 = c0, n1 = c1;
                    if (tt < 7) {
                        n0 = *(const float4*)(lp + (tt + 1) * EW);
                        n1 = *(const float4*)(lp + (tt + 1) * EW + 4);
                    }
                    dpstep32p(vF, c0, c1, lane, m1, m3, m5, m7, fD, hi);
                    c0 = n0; c1 = n1;
                }
            } else if (lim == 8) {
                float4 c0 = *(const float4*)(lp);
                float4 c1 = *(const float4*)(lp + 4);
#pragma unroll
                for (int tt = 0; tt < 8; tt++) {
                    float4 n0 = c0, n1 = c1;
                    if (tt < 7) {
                        n0 = *(const float4*)(lp + (tt + 1) * EW);
                        n1 = *(const float4*)(lp + (tt + 1) * EW + 4);
                    }
                    dpstep32p(vF, c0, c1, lane, m1, m3, m5, m7, fD, hi);
                    c0 = n0; c1 = n1;
                }
            } else {
                for (int tt = 0; tt < lim; tt++) {
                    float4 e0 = *(const float4*)(lp + tt * EW);
                    float4 e1 = *(const float4*)(lp + tt * EW + 4);
                    dpstep32p(vF, e0, e1, lane, m1, m3, m5, m7, fD, hi);
                }
            }
            if (ib < ADOPT_BLKS) renormF(vF, exF, lane, fD);
            else renormFc(vF, exF, lane, fD);
            hi = __shfl_up_sync(0xffffffffu, vF[7], 1);  // re-sync after rescale
            ISSUE_F(ib + 2);
        }
    } else {
        // ---------------- backward warp ----------------
        eshb[0][8 * EW + lane] = 0.0f; eshb[0][8 * EW + 32 + lane] = 0.0f;
        eshb[1][8 * EW + lane] = 0.0f; eshb[1][8 * EW + 32 + lane] = 0.0f;
        __syncwarp();

        const int s0 = lane * 8;
        float a1 = 0, a3 = 0, a5 = 0, a7 = 0;  // allow(s+2) for odd j
        {
            const int* lb = labels + b * LL;
#pragma unroll
            for (int j = 1; j < 8; j += 2) {
                int sp = s0 + j + 2;
                float a = 0.0f;
                if (sp <= 200) {
                    int i = sp >> 1;
                    a = (lb[i] != lb[i - 1]) ? 1.0f : 0.0f;
                }
                if (j == 1) a1 = a; else if (j == 3) a3 = a;
                else if (j == 5) a5 = a; else a7 = a;
            }
        }

        const unsigned ebase = smem_u32(&eshb[0][0]);
        const int rb = len - 1 - c;               // rows len-1 .. c+1
        const int nbb = (rb + 7) >> 3;

#define ISSUE_B(k) do {                                                          \
        if ((k) < nbb) {                                                         \
            const char* _s = gbase + (size_t)(len - 8 - 8 * (k)) * 832 + lane * 16; \
            unsigned _d = ebase + (((k) & 1) * (BUF * 4)) + lane * 16;           \
            _Pragma("unroll")                                                    \
            for (int _k = 0; _k < 13; _k++) cp_async16(_d + _k * 512, _s + _k * 512); \
        }                                                                        \
        asm volatile("cp.async.commit_group;" ::: "memory");                     \
    } while (0)

        ISSUE_B(0);
        ISSUE_B(1);

        const int end = 2 * label_lengths[b];
        float vB[8];
#pragma unroll
        for (int j = 0; j < 8; j++) {
            int s = s0 + j;
            vB[j] = (s == end || s == end - 1) ? 1.0f : 0.0f;
        }
        int exB = 0;
        float fD = 1.0f;
        float h0p = __shfl_down_sync(0xffffffffu, vB[0], 1);
        float h1p = __shfl_down_sync(0xffffffffu, vB[1], 1);

        for (int k = 0; k < nbb; k++) {
            asm volatile("cp.async.wait_group 1;" ::: "memory");
            const float* base = &eshb[k & 1][0];
            const float* lp = base + lane * 8;
            const float* lp2 = base + (lane + 1) * 8;  // right lane's e0.x/e0.y
            const int hi = len - 1 - 8 * k;
            const int lim = min(8, hi - c);           // consume rows 7..8-lim
            if (lim == 8) {
                float4 c0 = *(const float4*)(lp + 7 * EW);
                float4 c1 = *(const float4*)(lp + 7 * EW + 4);
                float2 c2 = *(const float2*)(lp2 + 7 * EW);
#pragma unroll
                for (int tt = 0; tt < 8; tt++) {
                    float4 n0 = c0, n1 = c1;
                    float2 n2 = c2;
                    if (tt < 7) {
                        n0 = *(const float4*)(lp + (6 - tt) * EW);
                        n1 = *(const float4*)(lp + (6 - tt) * EW + 4);
                        n2 = *(const float2*)(lp2 + (6 - tt) * EW);
                    }
                    bstep32p(vB, c0, c1, c2.x, c2.y, lane, a1, a3, a5, a7, fD,
                             h0p, h1p);
                    c0 = n0; c1 = n1; c2 = n2;
                }
            } else {
                for (int tt = 0; tt < lim; tt++) {
                    float4 e0 = *(const float4*)(lp + (7 - tt) * EW);
                    float4 e1 = *(const float4*)(lp + (7 - tt) * EW + 4);
                    float2 e2 = *(const float2*)(lp2 + (7 - tt) * EW);
                    bstep32p(vB, e0, e1, e2.x, e2.y, lane, a1, a3, a5, a7, fD,
                             h0p, h1p);
                }
            }
            if (k < ADOPT_BLKS) renormB(vB, exB, lane, fD);
            else renormBc(vB, exB, lane, fD);
            h0p = __shfl_down_sync(0xffffffffu, vB[0], 1);  // re-sync after rescale
            h1p = __shfl_down_sync(0xffffffffu, vB[1], 1);
            ISSUE_B(k + 2);
        }

        // publish beta_c frames
#pragma unroll
        for (int j = 0; j < 8; j++) sB[s0 + j] = vB[j];
        sExB[lane] = exB;
    }
    __syncthreads();

    if (w == 0) {
        // Total = sum_s alpha_c[s] * beta_c[s]
        float p = 0.0f;
        const int s0 = lane * 8;
#pragma unroll
        for (int j = 0; j < 8; j++) p += vF[j] * sB[s0 + j];
        const int e = exF + sExB[lane];
        int exv = (p > 0.0f) ? e : (int)0xC0000000;
        int exm = exv;
#pragma unroll
        for (int o = 16; o; o >>= 1) exm = max(exm, __shfl_xor_sync(0xffffffffu, exm, o));
        float a = (p > 0.0f) ? p * exp2f((float)(e - exm)) : 0.0f;
        a = warp_sum(a);
        if (lane == 0) { s_tot = a; s_ex = exm; }
    }
    __syncthreads();
    if (tid == 0) {
        const double lognum = log((double)s_tot) + (double)s_ex * LN2D + (double)s_corr;
        const float nll = -(float)lognum;
        g_cost[b] = s_den - (1.0f + LAMB) * nll;

        // ---- fused finalize: last CTA to arrive computes the mean ----
        __threadfence();
        const int arrived = atomicAdd(&g_cnt, 1);
        if (arrived == BB - 1) {
            float s = 0.0f;
#pragma unroll
            for (int i = 0; i < BB; i++) s += g_cost[i];
            out[0] = s / (float)BB;
            g_cnt = 0;  // reset for next graph replay
        }
    }
}

extern "C" void kernel_launch(void* const* d_in, const int* in_sizes, int n_in,
                              void* d_out, int out_size) {
    const float* logits = (const float*)d_in[0];
    const int* labels = (const int*)d_in[1];
    const int* input_lengths = (const int*)d_in[2];
    const int* label_lengths = (const int*)d_in[3];
    float* out = (float*)d_out;

    dim3 g1(TT, BB);
    lse_gather_kernel<<<g1, 256>>>(logits, labels, input_lengths);
    ctc_dp_kernel<<<BB, 96>>>(labels, input_lengths, label_lengths, out);
}